// round 2
// baseline (speedup 1.0000x reference)
#include <cuda_runtime.h>
#include <cstdint>

// ESN: out[b,p,l] via elementwise-diagonal recurrence.
// B=32, D_IN=64, D_STATE=1024, L=2048, LEAK=0.5
// v2: 2 lanes per chain (even/odd split of DIN), shfl-combine.
#define BB 32
#define DIN 64
#define DST 1024
#define LL 2048
#define TT 32      // timestep chunk
#define PTILE 64   // chains per block
#define NTHR 128   // 2 lanes per chain

__device__ __forceinline__ unsigned long long pack2(float a, float b) {
    unsigned long long r;
    asm("mov.b64 %0,{%1,%2};" : "=l"(r) : "f"(a), "f"(b));
    return r;
}
__device__ __forceinline__ void unpack2(unsigned long long v, float& a, float& b) {
    asm("mov.b64 {%0,%1},%2;" : "=f"(a), "=f"(b) : "l"(v));
}
__device__ __forceinline__ void ffma2(unsigned long long& acc,
                                      unsigned long long a, unsigned long long b) {
    asm("fma.rn.f32x2 %0,%1,%2,%0;" : "+l"(acc) : "l"(a), "l"(b));
}
__device__ __forceinline__ unsigned long long fadd2(unsigned long long a,
                                                    unsigned long long b) {
    unsigned long long r;
    asm("add.rn.f32x2 %0,%1,%2;" : "=l"(r) : "l"(a), "l"(b));
    return r;
}
// Accurate tanh (~1e-7 rel): avoids tanh.approx (abs err ~5e-4, too close to tol).
__device__ __forceinline__ float fast_tanh(float v) {
    float a = fabsf(v);
    float e = __expf(-2.0f * a);
    float r = __fdividef(1.0f - e, 1.0f + e);
    return copysignf(r, v);
}

__global__ __launch_bounds__(NTHR) void esn_kernel(
    const float* __restrict__ u,      // [B, DIN, L]
    const float* __restrict__ w_in,   // [DST, DIN]
    const float* __restrict__ w_hh,   // [DST, DST] (diagonal used)
    const float* __restrict__ bias,   // [DST]
    float* __restrict__ out)          // [B, DST, L]
{
    __shared__ __align__(16) float su[TT][68];     // [t][h], row stride 272B (16B mult)
    __shared__ float tile[PTILE][TT + 1];          // output transpose tile

    const int tid  = threadIdx.x;
    const int c    = tid >> 1;          // chain within block: 0..63
    const int half = tid & 1;           // which 32 of the 64 inputs
    const int b    = blockIdx.y;
    const int p0   = blockIdx.x * PTILE;
    const int p    = p0 + c;

    // This lane's half of the w_in row: 32 floats = 16 packed f32x2.
    unsigned long long W2[16];
    const float4* wrow = (const float4*)(w_in + (size_t)p * DIN + half * 32);
#pragma unroll
    for (int i = 0; i < 8; i++) {
        float4 v = wrow[i];
        W2[2 * i]     = pack2(v.x, v.y);
        W2[2 * i + 1] = pack2(v.z, v.w);
    }
    const float d_p    = w_hh[(size_t)p * DST + p];
    const float bias_p = bias[p];

    const float* ub = u + (size_t)b * DIN * LL;
    float*       ob = out + ((size_t)b * DST + p0) * LL;

    float x = 0.0f;

    for (int l0 = 0; l0 < LL; l0 += TT) {
        // ---- stage u[b, :, l0:l0+TT] into su[t][h] (transposed) ----
#pragma unroll
        for (int k = 0; k < 4; k++) {
            int idx = tid + k * NTHR;       // 0..511 = 64h x 8 quad-timesteps
            int h   = idx >> 3;
            int tq  = (idx & 7) << 2;
            float4 v = *(const float4*)(ub + (size_t)h * LL + l0 + tq);
            su[tq + 0][h] = v.x;
            su[tq + 1][h] = v.y;
            su[tq + 2][h] = v.z;
            su[tq + 3][h] = v.w;
        }
        __syncthreads();

        // ---- 32 recurrence steps ----
#pragma unroll
        for (int t = 0; t < TT; t++) {
            // This lane's 32 u-values: 8 x 16B broadcast LDS (half-warp groups share addr)
            const ulonglong2* s = (const ulonglong2*)(&su[t][half * 32]);
            unsigned long long a0 = 0ull, a1 = 0ull, a2 = 0ull, a3 = 0ull;
#pragma unroll
            for (int i = 0; i < 4; i++) {
                ulonglong2 v0 = s[2 * i];
                ulonglong2 v1 = s[2 * i + 1];
                ffma2(a0, W2[4 * i],     v0.x);
                ffma2(a1, W2[4 * i + 1], v0.y);
                ffma2(a2, W2[4 * i + 2], v1.x);
                ffma2(a3, W2[4 * i + 3], v1.y);
            }
            unsigned long long asum = fadd2(fadd2(a0, a1), fadd2(a2, a3));
            float lo, hi;
            unpack2(asum, lo, hi);
            float part = lo + hi;                       // this lane's half-dot
            float tot  = part + __shfl_xor_sync(0xffffffffu, part, 1);
            float pre  = fmaf(d_p, x, tot + bias_p);
            x = fmaf(0.5f, fast_tanh(pre), 0.5f * x);   // both lanes keep x in sync
            if (half == 0) tile[c][t] = x;              // one store per chain
        }
        __syncthreads();

        // ---- coalesced output write via transpose tile ----
#pragma unroll
        for (int r = 0; r < 16; r++) {
            int row = (tid >> 5) + r * 4;               // 4 warps x 16 iters = 64 rows
            int col = tid & 31;
            ob[(size_t)row * LL + l0 + col] = tile[row][col];
        }
        __syncthreads();
    }
}

extern "C" void kernel_launch(void* const* d_in, const int* in_sizes, int n_in,
                              void* d_out, int out_size) {
    const float* u    = (const float*)d_in[0];
    const float* w_in = (const float*)d_in[1];
    const float* w_hh = (const float*)d_in[2];
    const float* bias = (const float*)d_in[3];
    float* out = (float*)d_out;

    dim3 grid(DST / PTILE, BB);   // (16, 32) = 512 blocks, 128 thr each
    esn_kernel<<<grid, NTHR>>>(u, w_in, w_hh, bias, out);
}

// round 4
// speedup vs baseline: 1.5975x; 1.5975x over previous
#include <cuda_runtime.h>
#include <cstdint>

// ESN: out[b,p,l], elementwise-diagonal recurrence.
// B=32, D_IN=64, D_STATE=1024, L=2048, LEAK=0.5
// v3: v1 dataflow (full-warp LDS broadcast) + 255-reg budget for deep load
//     pipelining + double-buffered staging + short-critical-path tanh.
#define BB 32
#define DIN 64
#define DST 1024
#define LL 2048
#define TT 32
#define PTILE 128

__device__ __forceinline__ unsigned long long pack2(float a, float b) {
    unsigned long long r;
    asm("mov.b64 %0,{%1,%2};" : "=l"(r) : "f"(a), "f"(b));
    return r;
}
__device__ __forceinline__ void unpack2(unsigned long long v, float& a, float& b) {
    asm("mov.b64 {%0,%1},%2;" : "=f"(a), "=f"(b) : "l"(v));
}
__device__ __forceinline__ void ffma2(unsigned long long& acc,
                                      unsigned long long a, unsigned long long b) {
    asm("fma.rn.f32x2 %0,%1,%2,%0;" : "+l"(acc) : "l"(a), "l"(b));
}
__device__ __forceinline__ unsigned long long fadd2(unsigned long long a,
                                                    unsigned long long b) {
    unsigned long long r;
    asm("add.rn.f32x2 %0,%1,%2;" : "=l"(r) : "l"(a), "l"(b));
    return r;
}
__device__ __forceinline__ float ex2f(float v) {
    float r; asm("ex2.approx.f32 %0,%1;" : "=f"(r) : "f"(v)); return r;
}
__device__ __forceinline__ float rcpf(float v) {
    float r; asm("rcp.approx.f32 %0,%1;" : "=f"(r) : "f"(v)); return r;
}

__global__ __launch_bounds__(PTILE, 2) void esn_kernel(
    const float* __restrict__ u,      // [B, DIN, L]
    const float* __restrict__ w_in,   // [DST, DIN]
    const float* __restrict__ w_hh,   // [DST, DST] (diagonal used)
    const float* __restrict__ bias,   // [DST]
    float* __restrict__ out)          // [B, DST, L]
{
    __shared__ __align__(16) float su[2][TT][68];  // double-buffered [t][h]
    __shared__ float tile[PTILE][TT + 1];

    const int tid = threadIdx.x;
    const int b   = blockIdx.y;
    const int p0  = blockIdx.x * PTILE;
    const int p   = p0 + tid;

    // w_in row as 32 packed f32x2.
    unsigned long long W2[DIN / 2];
    const float4* wrow = (const float4*)(w_in + (size_t)p * DIN);
#pragma unroll
    for (int i = 0; i < DIN / 4; i++) {
        float4 v = wrow[i];
        W2[2 * i]     = pack2(v.x, v.y);
        W2[2 * i + 1] = pack2(v.z, v.w);
    }
    // Fold 2*log2(e) into the recurrence constants:
    //   pre2 = (u_dot + bias + d_p*x) * 2*log2e
    //   tanh(pre) = 1 - 2/(2^pre2 + 1)
    //   x' = 0.5x + 0.5*tanh = fma(0.5,x,0.5) - rcp(ex2(pre2)+1)
    const float K2 = 2.8853900817779268f;           // 2*log2(e)
    const float d2 = w_hh[(size_t)p * DST + p] * K2;
    const float b2 = bias[p] * K2;

    const float* ub = u + (size_t)b * DIN * LL;
    float*       ob = out + ((size_t)b * DST + p0) * LL;

    // staging geometry: 4 float4 per thread cover 64h x 32l
    const int h0 = (tid + 0 * PTILE) >> 3, t0 = ((tid + 0 * PTILE) & 7) << 2;
    const int h1 = (tid + 1 * PTILE) >> 3, t1 = ((tid + 1 * PTILE) & 7) << 2;
    const int h2 = (tid + 2 * PTILE) >> 3, t2 = ((tid + 2 * PTILE) & 7) << 2;
    const int h3 = (tid + 3 * PTILE) >> 3, t3 = ((tid + 3 * PTILE) & 7) << 2;

    float4 g0, g1, g2, g3;
    // prologue: stage chunk 0
    g0 = *(const float4*)(ub + (size_t)h0 * LL + t0);
    g1 = *(const float4*)(ub + (size_t)h1 * LL + t1);
    g2 = *(const float4*)(ub + (size_t)h2 * LL + t2);
    g3 = *(const float4*)(ub + (size_t)h3 * LL + t3);
    su[0][t0 + 0][h0] = g0.x; su[0][t0 + 1][h0] = g0.y; su[0][t0 + 2][h0] = g0.z; su[0][t0 + 3][h0] = g0.w;
    su[0][t1 + 0][h1] = g1.x; su[0][t1 + 1][h1] = g1.y; su[0][t1 + 2][h1] = g1.z; su[0][t1 + 3][h1] = g1.w;
    su[0][t2 + 0][h2] = g2.x; su[0][t2 + 1][h2] = g2.y; su[0][t2 + 2][h2] = g2.z; su[0][t2 + 3][h2] = g2.w;
    su[0][t3 + 0][h3] = g3.x; su[0][t3 + 1][h3] = g3.y; su[0][t3 + 2][h3] = g3.z; su[0][t3 + 3][h3] = g3.w;
    __syncthreads();

    float x = 0.0f;
    const int NCH = LL / TT;  // 64 chunks

    for (int c = 0; c < NCH; c++) {
        const int cur = c & 1, nxt = cur ^ 1;
        const int l0 = c * TT;

        // issue next chunk's global loads early (held in regs through compute)
        if (c + 1 < NCH) {
            const float* un = ub + (size_t)(l0 + TT);
            g0 = *(const float4*)(un + (size_t)h0 * LL + t0);
            g1 = *(const float4*)(un + (size_t)h1 * LL + t1);
            g2 = *(const float4*)(un + (size_t)h2 * LL + t2);
            g3 = *(const float4*)(un + (size_t)h3 * LL + t3);
        }

        // ---- 32 recurrence steps; all dots independent -> deep pipelining ----
#pragma unroll 8
        for (int t = 0; t < TT; t++) {
            const ulonglong2* s = (const ulonglong2*)(&su[cur][t][0]);
            ulonglong2 v0 = s[0], v1 = s[1], v2 = s[2], v3 = s[3];
            ulonglong2 v4 = s[4], v5 = s[5], v6 = s[6], v7 = s[7];
            unsigned long long a0 = 0ull, a1 = 0ull, a2 = 0ull, a3 = 0ull;
            ffma2(a0, W2[0],  v0.x); ffma2(a1, W2[1],  v0.y);
            ffma2(a2, W2[2],  v1.x); ffma2(a3, W2[3],  v1.y);
            ffma2(a0, W2[4],  v2.x); ffma2(a1, W2[5],  v2.y);
            ffma2(a2, W2[6],  v3.x); ffma2(a3, W2[7],  v3.y);
            ffma2(a0, W2[8],  v4.x); ffma2(a1, W2[9],  v4.y);
            ffma2(a2, W2[10], v5.x); ffma2(a3, W2[11], v5.y);
            ffma2(a0, W2[12], v6.x); ffma2(a1, W2[13], v6.y);
            ffma2(a2, W2[14], v7.x); ffma2(a3, W2[15], v7.y);
            ulonglong2 w0 = s[8],  w1 = s[9],  w2 = s[10], w3 = s[11];
            ulonglong2 w4 = s[12], w5 = s[13], w6 = s[14], w7 = s[15];
            ffma2(a0, W2[16], w0.x); ffma2(a1, W2[17], w0.y);
            ffma2(a2, W2[18], w1.x); ffma2(a3, W2[19], w1.y);
            ffma2(a0, W2[20], w2.x); ffma2(a1, W2[21], w2.y);
            ffma2(a2, W2[22], w3.x); ffma2(a3, W2[23], w3.y);
            ffma2(a0, W2[24], w4.x); ffma2(a1, W2[25], w4.y);
            ffma2(a2, W2[26], w5.x); ffma2(a3, W2[27], w5.y);
            ffma2(a0, W2[28], w6.x); ffma2(a1, W2[29], w6.y);
            ffma2(a2, W2[30], w7.x); ffma2(a3, W2[31], w7.y);

            unsigned long long asum = fadd2(fadd2(a0, a1), fadd2(a2, a3));
            float lo, hi;
            unpack2(asum, lo, hi);
            float c2 = fmaf(lo + hi, K2, b2);     // off the x-critical-path
            // x-critical-path: FFMA(4) -> EX2(16) -> FADD(4) -> RCP(16) -> FADD(4)
            float pre2 = fmaf(d2, x, c2);
            float e    = ex2f(pre2);
            float r    = rcpf(e + 1.0f);
            x = fmaf(0.5f, x, 0.5f) - r;
            tile[tid][t] = x;
        }

        // stage next chunk into the other buffer
        if (c + 1 < NCH) {
            su[nxt][t0 + 0][h0] = g0.x; su[nxt][t0 + 1][h0] = g0.y;
            su[nxt][t0 + 2][h0] = g0.z; su[nxt][t0 + 3][h0] = g0.w;
            su[nxt][t1 + 0][h1] = g1.x; su[nxt][t1 + 1][h1] = g1.y;
            su[nxt][t1 + 2][h1] = g1.z; su[nxt][t1 + 3][h1] = g1.w;
            su[nxt][t2 + 0][h2] = g2.x; su[nxt][t2 + 1][h2] = g2.y;
            su[nxt][t2 + 2][h2] = g2.z; su[nxt][t2 + 3][h2] = g2.w;
            su[nxt][t3 + 0][h3] = g3.x; su[nxt][t3 + 1][h3] = g3.y;
            su[nxt][t3 + 2][h3] = g3.z; su[nxt][t3 + 3][h3] = g3.w;
        }
        __syncthreads();   // tile complete + next su staged

        // ---- coalesced output write via transpose tile ----
#pragma unroll
        for (int r = 0; r < TT; r++) {
            int row = (tid >> 5) + r * 4;
            int col = tid & 31;
            ob[(size_t)row * LL + l0 + col] = tile[row][col];
        }
        __syncthreads();   // tile consumed
    }
}

extern "C" void kernel_launch(void* const* d_in, const int* in_sizes, int n_in,
                              void* d_out, int out_size) {
    const float* u    = (const float*)d_in[0];
    const float* w_in = (const float*)d_in[1];
    const float* w_hh = (const float*)d_in[2];
    const float* bias = (const float*)d_in[3];
    float* out = (float*)d_out;

    dim3 grid(DST / PTILE, BB);   // (8, 32) = 256 blocks
    esn_kernel<<<grid, PTILE>>>(u, w_in, w_hh, bias, out);
}

// round 5
// speedup vs baseline: 1.8534x; 1.1602x over previous
#include <cuda_runtime.h>
#include <cstdint>

// ESN: out[b,p,l], elementwise-diagonal recurrence.
// B=32, D_IN=64, D_STATE=1024, L=2048, LEAK=0.5
// v4: per-chunk phase split — all 32 dot products (x-independent) computed
//     first with full ILP, then the 44-cyc/step scan runs on registers.
#define BB 32
#define DIN 64
#define DST 1024
#define LL 2048
#define TT 32
#define PTILE 128

__device__ __forceinline__ unsigned long long pack2(float a, float b) {
    unsigned long long r;
    asm("mov.b64 %0,{%1,%2};" : "=l"(r) : "f"(a), "f"(b));
    return r;
}
__device__ __forceinline__ void unpack2(unsigned long long v, float& a, float& b) {
    asm("mov.b64 {%0,%1},%2;" : "=f"(a), "=f"(b) : "l"(v));
}
__device__ __forceinline__ void ffma2(unsigned long long& acc,
                                      unsigned long long a, unsigned long long b) {
    asm("fma.rn.f32x2 %0,%1,%2,%0;" : "+l"(acc) : "l"(a), "l"(b));
}
__device__ __forceinline__ unsigned long long fadd2(unsigned long long a,
                                                    unsigned long long b) {
    unsigned long long r;
    asm("add.rn.f32x2 %0,%1,%2;" : "=l"(r) : "l"(a), "l"(b));
    return r;
}
__device__ __forceinline__ float ex2f(float v) {
    float r; asm("ex2.approx.f32 %0,%1;" : "=f"(r) : "f"(v)); return r;
}
__device__ __forceinline__ float rcpf(float v) {
    float r; asm("rcp.approx.f32 %0,%1;" : "=f"(r) : "f"(v)); return r;
}

__global__ __launch_bounds__(PTILE, 2) void esn_kernel(
    const float* __restrict__ u,      // [B, DIN, L]
    const float* __restrict__ w_in,   // [DST, DIN]
    const float* __restrict__ w_hh,   // [DST, DST] (diagonal used)
    const float* __restrict__ bias,   // [DST]
    float* __restrict__ out)          // [B, DST, L]
{
    __shared__ __align__(16) float su[2][TT][68];   // double-buffered [t][h]
    __shared__ __align__(16) float tile[PTILE][TT + 4];  // 144B row stride

    const int tid = threadIdx.x;
    const int b   = blockIdx.y;
    const int p0  = blockIdx.x * PTILE;
    const int p   = p0 + tid;

    // w_in row as 32 packed f32x2.
    unsigned long long W2[DIN / 2];
    const float4* wrow = (const float4*)(w_in + (size_t)p * DIN);
#pragma unroll
    for (int i = 0; i < DIN / 4; i++) {
        float4 v = wrow[i];
        W2[2 * i]     = pack2(v.x, v.y);
        W2[2 * i + 1] = pack2(v.z, v.w);
    }
    // tanh via base-2: x' = fma(0.5,x,0.5) - rcp(ex2(pre2)+1), pre2 = K2*pre
    const float K2 = 2.8853900817779268f;           // 2*log2(e)
    const float d2 = w_hh[(size_t)p * DST + p] * K2;
    const float b2 = bias[p] * K2;

    const float* ub = u + (size_t)b * DIN * LL;
    float*       ob = out + ((size_t)b * DST + p0) * LL;

    // staging geometry: 4 float4 per thread cover 64h x 32l
    const int h0 = (tid + 0 * PTILE) >> 3, t0 = ((tid + 0 * PTILE) & 7) << 2;
    const int h1 = (tid + 1 * PTILE) >> 3, t1 = ((tid + 1 * PTILE) & 7) << 2;
    const int h2 = (tid + 2 * PTILE) >> 3, t2 = ((tid + 2 * PTILE) & 7) << 2;
    const int h3 = (tid + 3 * PTILE) >> 3, t3 = ((tid + 3 * PTILE) & 7) << 2;

    float4 g0, g1, g2, g3;
    g0 = *(const float4*)(ub + (size_t)h0 * LL + t0);
    g1 = *(const float4*)(ub + (size_t)h1 * LL + t1);
    g2 = *(const float4*)(ub + (size_t)h2 * LL + t2);
    g3 = *(const float4*)(ub + (size_t)h3 * LL + t3);
    su[0][t0 + 0][h0] = g0.x; su[0][t0 + 1][h0] = g0.y; su[0][t0 + 2][h0] = g0.z; su[0][t0 + 3][h0] = g0.w;
    su[0][t1 + 0][h1] = g1.x; su[0][t1 + 1][h1] = g1.y; su[0][t1 + 2][h1] = g1.z; su[0][t1 + 3][h1] = g1.w;
    su[0][t2 + 0][h2] = g2.x; su[0][t2 + 1][h2] = g2.y; su[0][t2 + 2][h2] = g2.z; su[0][t2 + 3][h2] = g2.w;
    su[0][t3 + 0][h3] = g3.x; su[0][t3 + 1][h3] = g3.y; su[0][t3 + 2][h3] = g3.z; su[0][t3 + 3][h3] = g3.w;
    __syncthreads();

    float x = 0.0f;
    const int NCH = LL / TT;  // 64 chunks

    for (int c = 0; c < NCH; c++) {
        const int cur = c & 1, nxt = cur ^ 1;
        const int l0 = c * TT;

        // prefetch next chunk's globals (held in regs through compute)
        if (c + 1 < NCH) {
            const float* un = ub + (size_t)(l0 + TT);
            g0 = *(const float4*)(un + (size_t)h0 * LL + t0);
            g1 = *(const float4*)(un + (size_t)h1 * LL + t1);
            g2 = *(const float4*)(un + (size_t)h2 * LL + t2);
            g3 = *(const float4*)(un + (size_t)h3 * LL + t3);
        }

        // ===== PHASE 1: 32 independent dot products (no x involvement) =====
        float pre2[TT];
#pragma unroll
        for (int t = 0; t < TT; t++) {
            const ulonglong2* s = (const ulonglong2*)(&su[cur][t][0]);
            ulonglong2 v0 = s[0],  v1 = s[1],  v2 = s[2],  v3 = s[3];
            ulonglong2 v4 = s[4],  v5 = s[5],  v6 = s[6],  v7 = s[7];
            ulonglong2 v8 = s[8],  v9 = s[9],  vA = s[10], vB = s[11];
            ulonglong2 vC = s[12], vD = s[13], vE = s[14], vF = s[15];
            unsigned long long a0 = 0ull, a1 = 0ull, a2 = 0ull, a3 = 0ull;
            ffma2(a0, W2[0],  v0.x); ffma2(a1, W2[1],  v0.y);
            ffma2(a2, W2[2],  v1.x); ffma2(a3, W2[3],  v1.y);
            ffma2(a0, W2[4],  v2.x); ffma2(a1, W2[5],  v2.y);
            ffma2(a2, W2[6],  v3.x); ffma2(a3, W2[7],  v3.y);
            ffma2(a0, W2[8],  v4.x); ffma2(a1, W2[9],  v4.y);
            ffma2(a2, W2[10], v5.x); ffma2(a3, W2[11], v5.y);
            ffma2(a0, W2[12], v6.x); ffma2(a1, W2[13], v6.y);
            ffma2(a2, W2[14], v7.x); ffma2(a3, W2[15], v7.y);
            ffma2(a0, W2[16], v8.x); ffma2(a1, W2[17], v8.y);
            ffma2(a2, W2[18], v9.x); ffma2(a3, W2[19], v9.y);
            ffma2(a0, W2[20], vA.x); ffma2(a1, W2[21], vA.y);
            ffma2(a2, W2[22], vB.x); ffma2(a3, W2[23], vB.y);
            ffma2(a0, W2[24], vC.x); ffma2(a1, W2[25], vC.y);
            ffma2(a2, W2[26], vD.x); ffma2(a3, W2[27], vD.y);
            ffma2(a0, W2[28], vE.x); ffma2(a1, W2[29], vE.y);
            ffma2(a2, W2[30], vF.x); ffma2(a3, W2[31], vF.y);
            unsigned long long asum = fadd2(fadd2(a0, a1), fadd2(a2, a3));
            float lo, hi;
            unpack2(asum, lo, hi);
            pre2[t] = fmaf(lo + hi, K2, b2);
        }

        // ===== PHASE 2: scan (44-cyc chain, register-resident) =====
#pragma unroll
        for (int t = 0; t < TT; t++) {
            float p2 = fmaf(d2, x, pre2[t]);
            float e  = ex2f(p2);
            float r  = rcpf(e + 1.0f);
            x = fmaf(0.5f, x, 0.5f) - r;
            pre2[t] = x;                       // reuse regs as output buffer
        }
        // bulk store row to tile: 8x STS.128, 144B stride (conflict-free)
#pragma unroll
        for (int k = 0; k < TT / 4; k++) {
            *(float4*)&tile[tid][4 * k] =
                make_float4(pre2[4 * k], pre2[4 * k + 1], pre2[4 * k + 2], pre2[4 * k + 3]);
        }

        // stage next chunk into the other buffer
        if (c + 1 < NCH) {
            su[nxt][t0 + 0][h0] = g0.x; su[nxt][t0 + 1][h0] = g0.y;
            su[nxt][t0 + 2][h0] = g0.z; su[nxt][t0 + 3][h0] = g0.w;
            su[nxt][t1 + 0][h1] = g1.x; su[nxt][t1 + 1][h1] = g1.y;
            su[nxt][t1 + 2][h1] = g1.z; su[nxt][t1 + 3][h1] = g1.w;
            su[nxt][t2 + 0][h2] = g2.x; su[nxt][t2 + 1][h2] = g2.y;
            su[nxt][t2 + 2][h2] = g2.z; su[nxt][t2 + 3][h2] = g2.w;
            su[nxt][t3 + 0][h3] = g3.x; su[nxt][t3 + 1][h3] = g3.y;
            su[nxt][t3 + 2][h3] = g3.z; su[nxt][t3 + 3][h3] = g3.w;
        }
        __syncthreads();   // tile complete + next su staged

        // ===== output: transpose copy, 8x LDS.128 + STG.128 per thread =====
        {
            const int orow = tid >> 3;
            const int ocol = (tid & 7) << 2;
#pragma unroll
            for (int it = 0; it < 8; it++) {
                int row = orow + it * 16;
                float4 v = *(const float4*)&tile[row][ocol];
                *(float4*)(ob + (size_t)row * LL + l0 + ocol) = v;
            }
        }
        __syncthreads();   // tile consumed before next chunk overwrites
    }
}

extern "C" void kernel_launch(void* const* d_in, const int* in_sizes, int n_in,
                              void* d_out, int out_size) {
    const float* u    = (const float*)d_in[0];
    const float* w_in = (const float*)d_in[1];
    const float* w_hh = (const float*)d_in[2];
    const float* bias = (const float*)d_in[3];
    float* out = (float*)d_out;

    dim3 grid(DST / PTILE, BB);   // (8, 32) = 256 blocks
    esn_kernel<<<grid, PTILE>>>(u, w_in, w_hh, bias, out);
}